// round 15
// baseline (speedup 1.0000x reference)
#include <cuda_runtime.h>
#include <cuda_bf16.h>
#include <cstdint>

// Problem dims
#define BB 1024
#define CC 80
#define DW 300
#define DWP 304          // padded DW for aligned float4 rows
#define JJ 8000
#define ICH 2048

// ---- scratch layout in one device global (no allocations allowed) ----------
// Non-zeroed: adj. Zeroed: t (in adj block) + contiguous P..M (hgemm targets)
#define OFF_ADJ 0
#define SZ_ADJ  (CC*CC)
#define OFF_T   (OFF_ADJ + SZ_ADJ)
#define SZ_T    (CC)
#define OFF_P   (OFF_T + SZ_T)
#define SZ_P    (CC*DWP)
#define OFF_Q   (OFF_P + SZ_P)
#define SZ_Q    (CC*1024)
#define OFF_X1  (OFF_Q + SZ_Q)
#define SZ_X1   (CC*1024)
#define OFF_X2  (OFF_X1 + SZ_X1)
#define SZ_X2   (CC*2048)
#define OFF_CLS (OFF_X2 + SZ_X2)
#define SZ_CLS  (CC*JJ)
#define OFF_M   (OFF_CLS + SZ_CLS)
#define SZ_M    (CC*2048)
#define SZ_ZERO (SZ_P + SZ_Q + SZ_X1 + SZ_X2 + SZ_CLS + SZ_M)
#define SZ_TOT  (OFF_M + SZ_M)

__device__ float g_buf[SZ_TOT];

// ===========================================================================
// helpers
// ===========================================================================
__device__ __forceinline__ uint32_t smem_u32(const void* p) {
    uint32_t a;
    asm("{ .reg .u64 t; cvta.to.shared.u64 t, %1; cvt.u32.u64 %0, t; }"
        : "=r"(a) : "l"(p));
    return a;
}
__device__ __forceinline__ void ldsm4(uint32_t& r0, uint32_t& r1,
                                      uint32_t& r2, uint32_t& r3, uint32_t addr) {
    asm volatile("ldmatrix.sync.aligned.m8n8.x4.shared.b16 {%0,%1,%2,%3}, [%4];"
                 : "=r"(r0), "=r"(r1), "=r"(r2), "=r"(r3) : "r"(addr));
}
__device__ __forceinline__ void mma16816(float* c,
        uint32_t a0, uint32_t a1, uint32_t a2, uint32_t a3,
        uint32_t b0, uint32_t b1) {
    asm volatile("mma.sync.aligned.m16n8k16.row.col.f32.bf16.bf16.f32 "
                 "{%0,%1,%2,%3}, {%4,%5,%6,%7}, {%8,%9}, {%0,%1,%2,%3};"
                 : "+f"(c[0]), "+f"(c[1]), "+f"(c[2]), "+f"(c[3])
                 : "r"(a0), "r"(a1), "r"(a2), "r"(a3), "r"(b0), "r"(b1));
}
// fp32x4 -> packed bf16 hi pair-quad + lo pair-quad, via bf16x2 cvt.
__device__ __forceinline__ void split4(float4 v, uint2& hi, uint2& lo) {
    uint32_t h01, h23;
    asm("cvt.rn.bf16x2.f32 %0, %1, %2;" : "=r"(h01) : "f"(v.y), "f"(v.x));
    asm("cvt.rn.bf16x2.f32 %0, %1, %2;" : "=r"(h23) : "f"(v.w), "f"(v.z));
    float h0 = __uint_as_float(h01 << 16);
    float h1 = __uint_as_float(h01 & 0xFFFF0000u);
    float h2 = __uint_as_float(h23 << 16);
    float h3 = __uint_as_float(h23 & 0xFFFF0000u);
    uint32_t l01, l23;
    asm("cvt.rn.bf16x2.f32 %0, %1, %2;" : "=r"(l01) : "f"(v.y - h1), "f"(v.x - h0));
    asm("cvt.rn.bf16x2.f32 %0, %1, %2;" : "=r"(l23) : "f"(v.w - h3), "f"(v.z - h2));
    hi.x = h01; hi.y = h23; lo.x = l01; lo.y = l23;
}
__device__ __forceinline__ float4 leaky4(float4 v) {
    v.x = v.x > 0.f ? v.x : 0.2f * v.x;
    v.y = v.y > 0.f ? v.y : 0.2f * v.y;
    v.z = v.z > 0.f ? v.z : 0.2f * v.z;
    v.w = v.w > 0.f ? v.w : 0.2f * v.w;
    return v;
}

// ===========================================================================
// Tensor-core GEMM via mma.sync (HMMA; baseline PTX, safe at compute_103):
//   C[80, N] += A[80, K] * op(B), split bf16 (hi/lo, 3 terms), fp32 accum.
// Tile 80 x 128, k-tile 32 fp32 (smem 65KB double-buffered -> 2 CTA/SM).
// 320 threads = 10 warps (5m x 2n); warp m16 x n64 -> 8 acc chains.
// Split-K over gridDim.y (chunk % 4 == 0); atomicAdd into pre-zeroed C.
// Optional fused dot-product reduction: dot_out[m] += sum_n C_v[m,n]*dot_vec[n]
// (used to fold t = cls @ b_img into the cls GEMM).
// ===========================================================================
#define HRS 40
#define HA_ELEM (80 * HRS)                        // 3200
#define HB_ELEM (128 * HRS)                       // 5120
#define HBUF_ELEM (2 * HA_ELEM + 2 * HB_ELEM)     // 16640 bf16
#define HS_BYTES (2 * HBUF_ELEM * 2)              // 66560 B

template<bool BNK>
__global__ void __launch_bounds__(320, 2)
hgemm(const float* __restrict__ A, const float* __restrict__ B,
      float* __restrict__ C, const float* __restrict__ bias_n,
      const float* __restrict__ bias_m,
      const float* __restrict__ dot_vec, float* __restrict__ dot_out,
      int N, int K, int Kb, int lda, int ldb, int ldc, int leaky_b, int transC) {
    extern __shared__ __nv_bfloat16 hs[];
    const uint32_t sbase = smem_u32(hs);

    const int tid  = threadIdx.x;
    const int lane = tid & 31;
    const int wid  = tid >> 5;          // 0..9
    const int wm   = wid >> 1;          // 0..4 -> rows wm*16
    const int wn   = wid & 1;           // 0..1 -> cols wn*64
    const int n0   = blockIdx.x * 128;

    const int chunk = (K + gridDim.y - 1) / (int)gridDim.y;
    const int kb = min(K, (int)blockIdx.y * chunk);
    const int ke = min(K, kb + chunk);
    const int ntiles = (ke - kb + 31) >> 5;
    const int keB = min(ke, Kb);

    const uint32_t oAL = HA_ELEM;
    const uint32_t oBH = 2 * HA_ELEM, oBL = 2 * HA_ELEM + HB_ELEM;

    // ---- staging registers (k-tile 32)
    uint2 aH[2], aL[2];
    uint2 bH[4], bL[4];

    auto loadA = [&](int k0) {
        #pragma unroll
        for (int i = 0; i < 2; i++) {
            int idx = tid + i * 320;            // 80 rows x 8 float4 = 640
            int row = idx >> 3, c4 = idx & 7;
            int gk = k0 + c4 * 4;
            float4 v = make_float4(0.f, 0.f, 0.f, 0.f);
            if (gk < ke) v = *(const float4*)(A + (size_t)row * lda + gk);
            split4(v, aH[i], aL[i]);
        }
    };
    auto storeA = [&](int buf) {
        __nv_bfloat16* base = hs + buf * HBUF_ELEM;
        #pragma unroll
        for (int i = 0; i < 2; i++) {
            int idx = tid + i * 320;
            int row = idx >> 3, c4 = idx & 7;
            uint32_t off = row * HRS + c4 * 4;
            *(uint2*)(base + off) = aH[i];
            *(uint2*)(base + oAL + off) = aL[i];
        }
    };
    auto loadB = [&](int k0) {
        if (BNK) {
            #pragma unroll
            for (int i = 0; i < 4; i++) {
                int idx = tid + i * 320;        // 128 rows x 8 float4 = 1024
                if (idx >= 1024) continue;
                int row = idx >> 3, c4 = idx & 7;
                int gn = n0 + row, gk = k0 + c4 * 4;
                float4 v = make_float4(0.f, 0.f, 0.f, 0.f);
                if (gk < keB && gn < N)
                    v = *(const float4*)(B + (size_t)gn * ldb + gk);
                split4(v, bH[i], bL[i]);
            }
        } else {
            // B[K,N]: groups of 4 k-rows x 4 n-cols; 8 kq x 32 nq = 256 groups
            if (tid < 256) {
                int nq = tid & 31, kq = tid >> 5;
                int gn = n0 + nq * 4, gkb = k0 + kq * 4;
                float4 r[4];
                #pragma unroll
                for (int rr = 0; rr < 4; rr++) {
                    int gk = gkb + rr;
                    float4 v = make_float4(0.f, 0.f, 0.f, 0.f);
                    if (gk < keB && gn < N)
                        v = *(const float4*)(B + (size_t)gk * ldb + gn);
                    if (leaky_b) v = leaky4(v);
                    r[rr] = v;
                }
                #pragma unroll
                for (int j = 0; j < 4; j++) {
                    float4 kv = make_float4(((float*)&r[0])[j], ((float*)&r[1])[j],
                                            ((float*)&r[2])[j], ((float*)&r[3])[j]);
                    split4(kv, bH[j], bL[j]);
                }
            }
        }
    };
    auto storeB = [&](int buf) {
        __nv_bfloat16* base = hs + buf * HBUF_ELEM;
        if (BNK) {
            #pragma unroll
            for (int i = 0; i < 4; i++) {
                int idx = tid + i * 320;
                if (idx >= 1024) continue;
                int row = idx >> 3, c4 = idx & 7;
                uint32_t off = row * HRS + c4 * 4;
                *(uint2*)(base + oBH + off) = bH[i];
                *(uint2*)(base + oBL + off) = bL[i];
            }
        } else {
            if (tid < 256) {
                int nq = tid & 31, kq = tid >> 5;
                #pragma unroll
                for (int j = 0; j < 4; j++) {
                    uint32_t off = (nq * 4 + j) * HRS + kq * 4;
                    *(uint2*)(base + oBH + off) = bH[j];
                    *(uint2*)(base + oBL + off) = bL[j];
                }
            }
        }
    };

    float acc[8][4];
    #pragma unroll
    for (int i = 0; i < 8; i++)
        #pragma unroll
        for (int j = 0; j < 4; j++) acc[i][j] = 0.f;

    loadA(kb); loadB(kb);
    storeA(0); storeB(0);
    __syncthreads();

    const int grp = lane >> 3, lr = lane & 7;
    const uint32_t aRow = wm * 16 + ((grp & 1) << 3) + lr;
    const uint32_t aColOff = (grp >> 1) << 3;
    const uint32_t bRowBase = wn * 64 + ((grp >> 1) << 3) + lr;
    const uint32_t bColOff = (grp & 1) << 3;

    for (int t = 0; t < ntiles; t++) {
        const int cur = t & 1;
        const bool more = (t + 1 < ntiles);
        if (more) { int k0n = kb + (t + 1) * 32; loadA(k0n); loadB(k0n); }

        const uint32_t bufb = sbase + cur * (HBUF_ELEM * 2);

        #pragma unroll 1
        for (int t3 = 0; t3 < 3; t3++) {
            // term -> A base (hi,hi,lo), B base (hi,lo,hi)
            const uint32_t tA = bufb + ((t3 == 2) ? oAL * 2 : 0);
            const uint32_t tB = bufb + oBH * 2 + ((t3 == 1) ? HB_ELEM * 2 : 0);

            #pragma unroll
            for (int k16 = 0; k16 < 2; k16++) {
                uint32_t a0, a1, a2, a3;
                ldsm4(a0, a1, a2, a3,
                      tA + (aRow * HRS + k16 * 16 + aColOff) * 2);
                uint32_t b[16];
                #pragma unroll
                for (int h = 0; h < 4; h++) {
                    ldsm4(b[h*4], b[h*4+1], b[h*4+2], b[h*4+3],
                          tB + ((bRowBase + h * 16) * HRS + k16 * 16 + bColOff) * 2);
                }
                #pragma unroll
                for (int nt = 0; nt < 8; nt++)
                    mma16816(acc[nt], a0, a1, a2, a3, b[nt*2], b[nt*2+1]);
            }
        }

        if (more) { storeA(cur ^ 1); storeB(cur ^ 1); }
        __syncthreads();
    }

    // ---- epilogue (+ optional fused dot reduction into dot_out)
    const bool first = (blockIdx.y == 0);
    const int r0 = wm * 16 + (lane >> 2);
    const int cb = n0 + wn * 64 + (lane & 3) * 2;
    float s0 = 0.f, s1 = 0.f;
    #pragma unroll
    for (int nt = 0; nt < 8; nt++) {
        #pragma unroll
        for (int e = 0; e < 4; e++) {
            int gm = r0 + ((e >> 1) << 3);
            int gn = cb + nt * 8 + (e & 1);
            if (gn >= N) continue;
            float v = acc[nt][e];
            if (first) {
                if (bias_n) v += bias_n[gn];
                if (bias_m) v += bias_m[gm];
            }
            if (dot_out) {
                float bv = dot_vec[gn] * v;
                if (e >> 1) s1 += bv; else s0 += bv;
            }
            float* dst = transC ? (C + (size_t)gn * ldc + gm)
                                : (C + (size_t)gm * ldc + gn);
            atomicAdd(dst, v);
        }
    }
    if (dot_out) {
        s0 += __shfl_xor_sync(0xFFFFFFFFu, s0, 1);
        s0 += __shfl_xor_sync(0xFFFFFFFFu, s0, 2);
        s1 += __shfl_xor_sync(0xFFFFFFFFu, s1, 1);
        s1 += __shfl_xor_sync(0xFFFFFFFFu, s1, 2);
        if ((lane & 3) == 0) {
            atomicAdd(dot_out + r0, s0);
            atomicAdd(dot_out + r0 + 8, s1);
        }
    }
}

// ===========================================================================
// zero + adj in one launch: last block computes adj (and zeroes t), the rest
// zero the hgemm scratch + out.
// ===========================================================================
__global__ void zero_adj_kernel(float* __restrict__ z, int nz,
                                float* __restrict__ o, int no,
                                const float* __restrict__ A,
                                float* __restrict__ adj,
                                float* __restrict__ t) {
    if (blockIdx.x == gridDim.x - 1) {
        __shared__ float D[CC];
        int tid = threadIdx.x;
        if (tid < CC) {
            float s = 0.f;
            #pragma unroll 4
            for (int j = 0; j < CC; j++) s += A[tid * CC + j];
            D[tid] = 1.0f / sqrtf(s);
            t[tid] = 0.f;
        }
        __syncthreads();
        for (int idx = tid; idx < CC * CC; idx += blockDim.x) {
            int i = idx / CC, j = idx % CC;
            adj[idx] = D[i] * A[j * CC + i] * D[j];
        }
        return;
    }
    int i = blockIdx.x * blockDim.x + threadIdx.x;
    if (i < nz) z[i] = 0.f;
    else if (i - nz < no) o[i - nz] = 0.f;
}

// ===========================================================================
extern "C" void kernel_launch(void* const* d_in, const int* in_sizes, int n_in,
                              void* d_out, int out_size) {
    const float* feature = (const float*)d_in[0];   // [1024, 2048]
    const float* inp     = (const float*)d_in[1];   // [1, 80, 300]
    const float* A       = (const float*)d_in[2];   // [80, 80]
    const float* Wgc1    = (const float*)d_in[3];   // [300, 1024]
    const float* Wgc2    = (const float*)d_in[4];   // [1024, 2048]
    const float* Wimg    = (const float*)d_in[5];   // [8000, 2048]
    const float* bimg    = (const float*)d_in[6];   // [8000]
    const float* Wcls    = (const float*)d_in[7];   // [8000, 2048]
    const float* bcls    = (const float*)d_in[8];   // [8000]
    float* out = (float*)d_out;                     // [1024, 80] row-major

    float* buf;
    cudaGetSymbolAddress((void**)&buf, g_buf);
    float* adj = buf + OFF_ADJ;
    float* t   = buf + OFF_T;
    float* P   = buf + OFF_P;
    float* Q   = buf + OFF_Q;
    float* x1  = buf + OFF_X1;
    float* x2  = buf + OFF_X2;
    float* cls = buf + OFF_CLS;
    float* Mm  = buf + OFF_M;

    cudaFuncSetAttribute(hgemm<false>,
                         cudaFuncAttributeMaxDynamicSharedMemorySize, HS_BYTES);
    cudaFuncSetAttribute(hgemm<true>,
                         cudaFuncAttributeMaxDynamicSharedMemorySize, HS_BYTES);

    // Zero all hgemm targets (P..M contiguous) + out + t, plus adj, one launch.
    {
        int ntot = SZ_ZERO + BB * CC;
        int nblk = (ntot + 255) / 256 + 1;   // +1: adj block
        zero_adj_kernel<<<nblk, 256>>>(P, SZ_ZERO, out, BB * CC, A, adj, t);
    }

    // P = adj @ inp0                 [80,300]  K=80, split 4 (chunk 20)
    hgemm<false><<<dim3(3, 4), 320, HS_BYTES>>>(
        adj, inp, P, nullptr, nullptr, nullptr, nullptr,
        DW, CC, CC, CC, DW, DWP, 0, 0);

    // x1 = P @ W_gc1                 [80,1024] K=304 pad (Kb=300), split 4 (chunk 76)
    hgemm<false><<<dim3(8, 4), 320, HS_BYTES>>>(
        P, Wgc1, x1, nullptr, nullptr, nullptr, nullptr,
        1024, DWP, DW, DWP, 1024, 1024, 0, 0);

    // Q = adj @ leaky(x1)            [80,1024] K=80, split 4 (chunk 20)
    hgemm<false><<<dim3(8, 4), 320, HS_BYTES>>>(
        adj, x1, Q, nullptr, nullptr, nullptr, nullptr,
        1024, CC, CC, CC, 1024, 1024, 1, 0);

    // x2 = Q @ W_gc2                 [80,2048] K=1024, split 16 (chunk 64, 256 blk)
    hgemm<false><<<dim3(16, 16), 320, HS_BYTES>>>(
        Q, Wgc2, x2, nullptr, nullptr, nullptr, nullptr,
        2048, 1024, 1024, 1024, 2048, 2048, 0, 0);

    // cls = x2 @ W_cls^T + b_cls     [80,8000] K=2048, split 8 (chunk 256, 504 blk)
    // fused: t[c] += sum_n cls_partial[c,n] * b_img[n]
    hgemm<true><<<dim3(63, 8), 320, HS_BYTES>>>(
        x2, Wcls, cls, bcls, nullptr, bimg, t,
        JJ, 2048, 2048, 2048, 2048, JJ, 0, 0);

    // M = cls @ W_img                [80,2048] K=8000, split 20 (chunk 400, 320 blk)
    hgemm<false><<<dim3(16, 20), 320, HS_BYTES>>>(
        cls, Wimg, Mm, nullptr, nullptr, nullptr, nullptr,
        2048, JJ, JJ, JJ, 2048, 2048, 0, 0);

    // out^T: C[c,b] = Mm[c,:].feature[b,:] + t[c] -> out[b*80+c]
    //                                [80,1024] K=2048, split 32 (chunk 64, 256 blk)
    hgemm<true><<<dim3(8, 32), 320, HS_BYTES>>>(
        Mm, feature, out, nullptr, t, nullptr, nullptr,
        BB, 2048, 2048, 2048, 2048, CC, 0, 1);
}

// round 16
// speedup vs baseline: 1.1702x; 1.1702x over previous
#include <cuda_runtime.h>
#include <cuda_bf16.h>
#include <cstdint>

// Problem dims
#define BB 1024
#define CC 80
#define DW 300
#define DWP 304          // padded DW for aligned float4 rows
#define JJ 8000
#define ICH 2048

// ---- scratch layout in one device global (no allocations allowed) ----------
// Non-zeroed: adj. Zeroed: t (in adj block) + contiguous P..M (hgemm targets)
#define OFF_ADJ 0
#define SZ_ADJ  (CC*CC)
#define OFF_T   (OFF_ADJ + SZ_ADJ)
#define SZ_T    (CC)
#define OFF_P   (OFF_T + SZ_T)
#define SZ_P    (CC*DWP)
#define OFF_Q   (OFF_P + SZ_P)
#define SZ_Q    (CC*1024)
#define OFF_X1  (OFF_Q + SZ_Q)
#define SZ_X1   (CC*1024)
#define OFF_X2  (OFF_X1 + SZ_X1)
#define SZ_X2   (CC*2048)
#define OFF_CLS (OFF_X2 + SZ_X2)
#define SZ_CLS  (CC*JJ)
#define OFF_M   (OFF_CLS + SZ_CLS)
#define SZ_M    (CC*2048)
#define SZ_ZERO (SZ_P + SZ_Q + SZ_X1 + SZ_X2 + SZ_CLS + SZ_M)
#define SZ_TOT  (OFF_M + SZ_M)

__device__ float g_buf[SZ_TOT];

// ===========================================================================
// helpers
// ===========================================================================
__device__ __forceinline__ uint32_t smem_u32(const void* p) {
    uint32_t a;
    asm("{ .reg .u64 t; cvta.to.shared.u64 t, %1; cvt.u32.u64 %0, t; }"
        : "=r"(a) : "l"(p));
    return a;
}
__device__ __forceinline__ void ldsm4(uint32_t& r0, uint32_t& r1,
                                      uint32_t& r2, uint32_t& r3, uint32_t addr) {
    asm volatile("ldmatrix.sync.aligned.m8n8.x4.shared.b16 {%0,%1,%2,%3}, [%4];"
                 : "=r"(r0), "=r"(r1), "=r"(r2), "=r"(r3) : "r"(addr));
}
__device__ __forceinline__ void mma16816(float* c,
        uint32_t a0, uint32_t a1, uint32_t a2, uint32_t a3,
        uint32_t b0, uint32_t b1) {
    asm volatile("mma.sync.aligned.m16n8k16.row.col.f32.bf16.bf16.f32 "
                 "{%0,%1,%2,%3}, {%4,%5,%6,%7}, {%8,%9}, {%0,%1,%2,%3};"
                 : "+f"(c[0]), "+f"(c[1]), "+f"(c[2]), "+f"(c[3])
                 : "r"(a0), "r"(a1), "r"(a2), "r"(a3), "r"(b0), "r"(b1));
}
// fp32x4 -> packed bf16 hi pair-quad + lo pair-quad, via bf16x2 cvt.
__device__ __forceinline__ void split4(float4 v, uint2& hi, uint2& lo) {
    uint32_t h01, h23;
    asm("cvt.rn.bf16x2.f32 %0, %1, %2;" : "=r"(h01) : "f"(v.y), "f"(v.x));
    asm("cvt.rn.bf16x2.f32 %0, %1, %2;" : "=r"(h23) : "f"(v.w), "f"(v.z));
    float h0 = __uint_as_float(h01 << 16);
    float h1 = __uint_as_float(h01 & 0xFFFF0000u);
    float h2 = __uint_as_float(h23 << 16);
    float h3 = __uint_as_float(h23 & 0xFFFF0000u);
    uint32_t l01, l23;
    asm("cvt.rn.bf16x2.f32 %0, %1, %2;" : "=r"(l01) : "f"(v.y - h1), "f"(v.x - h0));
    asm("cvt.rn.bf16x2.f32 %0, %1, %2;" : "=r"(l23) : "f"(v.w - h3), "f"(v.z - h2));
    hi.x = h01; hi.y = h23; lo.x = l01; lo.y = l23;
}
__device__ __forceinline__ float4 leaky4(float4 v) {
    v.x = v.x > 0.f ? v.x : 0.2f * v.x;
    v.y = v.y > 0.f ? v.y : 0.2f * v.y;
    v.z = v.z > 0.f ? v.z : 0.2f * v.z;
    v.w = v.w > 0.f ? v.w : 0.2f * v.w;
    return v;
}

// ===========================================================================
// Tensor-core GEMM via mma.sync (HMMA; baseline PTX, safe at compute_103):
//   C[80, N] += A[80, K] * op(B), split bf16 (hi/lo, 3 terms), fp32 accum.
// Tile 80 x 128, k-tile 32 fp32 (smem 65KB double-buffered -> 2 CTA/SM).
// 320 threads = 10 warps (5m x 2n); warp m16 x n64 -> 8 acc chains.
// Split-K over gridDim.y (chunk % 4 == 0); atomicAdd into pre-zeroed C.
// Optional fused dot reduction: dot_out[m] += sum_n C_v[m,n]*dot_vec[n].
// PDL: griddepcontrol.wait before any dependent read; launch_dependents at end.
// ===========================================================================
#define HRS 40
#define HA_ELEM (80 * HRS)                        // 3200
#define HB_ELEM (128 * HRS)                       // 5120
#define HBUF_ELEM (2 * HA_ELEM + 2 * HB_ELEM)     // 16640 bf16
#define HS_BYTES (2 * HBUF_ELEM * 2)              // 66560 B

template<bool BNK>
__global__ void __launch_bounds__(320, 2)
hgemm(const float* __restrict__ A, const float* __restrict__ B,
      float* __restrict__ C, const float* __restrict__ bias_n,
      const float* __restrict__ bias_m,
      const float* __restrict__ dot_vec, float* __restrict__ dot_out,
      int N, int K, int Kb, int lda, int ldb, int ldc, int leaky_b, int transC) {
    extern __shared__ __nv_bfloat16 hs[];
    const uint32_t sbase = smem_u32(hs);

    const int tid  = threadIdx.x;
    const int lane = tid & 31;
    const int wid  = tid >> 5;          // 0..9
    const int wm   = wid >> 1;          // 0..4 -> rows wm*16
    const int wn   = wid & 1;           // 0..1 -> cols wn*64
    const int n0   = blockIdx.x * 128;

    const int chunk = (K + gridDim.y - 1) / (int)gridDim.y;
    const int kb = min(K, (int)blockIdx.y * chunk);
    const int ke = min(K, kb + chunk);
    const int ntiles = (ke - kb + 31) >> 5;
    const int keB = min(ke, Kb);

    const uint32_t oAL = HA_ELEM;
    const uint32_t oBH = 2 * HA_ELEM, oBL = 2 * HA_ELEM + HB_ELEM;

    // ---- staging registers (k-tile 32)
    uint2 aH[2], aL[2];
    uint2 bH[4], bL[4];

    auto loadA = [&](int k0) {
        #pragma unroll
        for (int i = 0; i < 2; i++) {
            int idx = tid + i * 320;            // 80 rows x 8 float4 = 640
            int row = idx >> 3, c4 = idx & 7;
            int gk = k0 + c4 * 4;
            float4 v = make_float4(0.f, 0.f, 0.f, 0.f);
            if (gk < ke) v = *(const float4*)(A + (size_t)row * lda + gk);
            split4(v, aH[i], aL[i]);
        }
    };
    auto storeA = [&](int buf) {
        __nv_bfloat16* base = hs + buf * HBUF_ELEM;
        #pragma unroll
        for (int i = 0; i < 2; i++) {
            int idx = tid + i * 320;
            int row = idx >> 3, c4 = idx & 7;
            uint32_t off = row * HRS + c4 * 4;
            *(uint2*)(base + off) = aH[i];
            *(uint2*)(base + oAL + off) = aL[i];
        }
    };
    auto loadB = [&](int k0) {
        if (BNK) {
            #pragma unroll
            for (int i = 0; i < 4; i++) {
                int idx = tid + i * 320;        // 128 rows x 8 float4 = 1024
                if (idx >= 1024) continue;
                int row = idx >> 3, c4 = idx & 7;
                int gn = n0 + row, gk = k0 + c4 * 4;
                float4 v = make_float4(0.f, 0.f, 0.f, 0.f);
                if (gk < keB && gn < N)
                    v = *(const float4*)(B + (size_t)gn * ldb + gk);
                split4(v, bH[i], bL[i]);
            }
        } else {
            // B[K,N]: groups of 4 k-rows x 4 n-cols; 8 kq x 32 nq = 256 groups
            if (tid < 256) {
                int nq = tid & 31, kq = tid >> 5;
                int gn = n0 + nq * 4, gkb = k0 + kq * 4;
                float4 r[4];
                #pragma unroll
                for (int rr = 0; rr < 4; rr++) {
                    int gk = gkb + rr;
                    float4 v = make_float4(0.f, 0.f, 0.f, 0.f);
                    if (gk < keB && gn < N)
                        v = *(const float4*)(B + (size_t)gk * ldb + gn);
                    if (leaky_b) v = leaky4(v);
                    r[rr] = v;
                }
                #pragma unroll
                for (int j = 0; j < 4; j++) {
                    float4 kv = make_float4(((float*)&r[0])[j], ((float*)&r[1])[j],
                                            ((float*)&r[2])[j], ((float*)&r[3])[j]);
                    split4(kv, bH[j], bL[j]);
                }
            }
        }
    };
    auto storeB = [&](int buf) {
        __nv_bfloat16* base = hs + buf * HBUF_ELEM;
        if (BNK) {
            #pragma unroll
            for (int i = 0; i < 4; i++) {
                int idx = tid + i * 320;
                if (idx >= 1024) continue;
                int row = idx >> 3, c4 = idx & 7;
                uint32_t off = row * HRS + c4 * 4;
                *(uint2*)(base + oBH + off) = bH[i];
                *(uint2*)(base + oBL + off) = bL[i];
            }
        } else {
            if (tid < 256) {
                int nq = tid & 31, kq = tid >> 5;
                #pragma unroll
                for (int j = 0; j < 4; j++) {
                    uint32_t off = (nq * 4 + j) * HRS + kq * 4;
                    *(uint2*)(base + oBH + off) = bH[j];
                    *(uint2*)(base + oBL + off) = bL[j];
                }
            }
        }
    };

    float acc[8][4];
    #pragma unroll
    for (int i = 0; i < 8; i++)
        #pragma unroll
        for (int j = 0; j < 4; j++) acc[i][j] = 0.f;

    // PDL: block until the upstream grid (our input producer) is complete.
    asm volatile("griddepcontrol.wait;" ::: "memory");

    loadA(kb); loadB(kb);
    storeA(0); storeB(0);
    __syncthreads();

    const int grp = lane >> 3, lr = lane & 7;
    const uint32_t aRow = wm * 16 + ((grp & 1) << 3) + lr;
    const uint32_t aColOff = (grp >> 1) << 3;
    const uint32_t bRowBase = wn * 64 + ((grp >> 1) << 3) + lr;
    const uint32_t bColOff = (grp & 1) << 3;

    for (int t = 0; t < ntiles; t++) {
        const int cur = t & 1;
        const bool more = (t + 1 < ntiles);
        if (more) { int k0n = kb + (t + 1) * 32; loadA(k0n); loadB(k0n); }

        const uint32_t bufb = sbase + cur * (HBUF_ELEM * 2);

        #pragma unroll 1
        for (int t3 = 0; t3 < 3; t3++) {
            // term -> A base (hi,hi,lo), B base (hi,lo,hi)
            const uint32_t tA = bufb + ((t3 == 2) ? oAL * 2 : 0);
            const uint32_t tB = bufb + oBH * 2 + ((t3 == 1) ? HB_ELEM * 2 : 0);

            #pragma unroll
            for (int k16 = 0; k16 < 2; k16++) {
                uint32_t a0, a1, a2, a3;
                ldsm4(a0, a1, a2, a3,
                      tA + (aRow * HRS + k16 * 16 + aColOff) * 2);
                uint32_t b[16];
                #pragma unroll
                for (int h = 0; h < 4; h++) {
                    ldsm4(b[h*4], b[h*4+1], b[h*4+2], b[h*4+3],
                          tB + ((bRowBase + h * 16) * HRS + k16 * 16 + bColOff) * 2);
                }
                #pragma unroll
                for (int nt = 0; nt < 8; nt++)
                    mma16816(acc[nt], a0, a1, a2, a3, b[nt*2], b[nt*2+1]);
            }
        }

        if (more) { storeA(cur ^ 1); storeB(cur ^ 1); }
        __syncthreads();
    }

    // ---- epilogue (+ optional fused dot reduction into dot_out)
    const bool first = (blockIdx.y == 0);
    const int r0 = wm * 16 + (lane >> 2);
    const int cb = n0 + wn * 64 + (lane & 3) * 2;
    float s0 = 0.f, s1 = 0.f;
    #pragma unroll
    for (int nt = 0; nt < 8; nt++) {
        #pragma unroll
        for (int e = 0; e < 4; e++) {
            int gm = r0 + ((e >> 1) << 3);
            int gn = cb + nt * 8 + (e & 1);
            if (gn >= N) continue;
            float v = acc[nt][e];
            if (first) {
                if (bias_n) v += bias_n[gn];
                if (bias_m) v += bias_m[gm];
            }
            if (dot_out) {
                float bv = dot_vec[gn] * v;
                if (e >> 1) s1 += bv; else s0 += bv;
            }
            float* dst = transC ? (C + (size_t)gn * ldc + gm)
                                : (C + (size_t)gm * ldc + gn);
            atomicAdd(dst, v);
        }
    }
    if (dot_out) {
        s0 += __shfl_xor_sync(0xFFFFFFFFu, s0, 1);
        s0 += __shfl_xor_sync(0xFFFFFFFFu, s0, 2);
        s1 += __shfl_xor_sync(0xFFFFFFFFu, s1, 1);
        s1 += __shfl_xor_sync(0xFFFFFFFFu, s1, 2);
        if ((lane & 3) == 0) {
            atomicAdd(dot_out + r0, s0);
            atomicAdd(dot_out + r0 + 8, s1);
        }
    }
    // PDL: all our writes are done; allow the dependent grid to proceed.
    asm volatile("griddepcontrol.launch_dependents;" ::: "memory");
}

// ===========================================================================
// zero + adj in one launch: last block computes adj (and zeroes t), the rest
// zero the hgemm scratch + out.
// ===========================================================================
__global__ void zero_adj_kernel(float* __restrict__ z, int nz,
                                float* __restrict__ o, int no,
                                const float* __restrict__ A,
                                float* __restrict__ adj,
                                float* __restrict__ t) {
    if (blockIdx.x == gridDim.x - 1) {
        __shared__ float D[CC];
        int tid = threadIdx.x;
        if (tid < CC) {
            float s = 0.f;
            #pragma unroll 4
            for (int j = 0; j < CC; j++) s += A[tid * CC + j];
            D[tid] = 1.0f / sqrtf(s);
            t[tid] = 0.f;
        }
        __syncthreads();
        for (int idx = tid; idx < CC * CC; idx += blockDim.x) {
            int i = idx / CC, j = idx % CC;
            adj[idx] = D[i] * A[j * CC + i] * D[j];
        }
        return;
    }
    int i = blockIdx.x * blockDim.x + threadIdx.x;
    if (i < nz) z[i] = 0.f;
    else if (i - nz < no) o[i - nz] = 0.f;
}

// ---- PDL launch helper ----------------------------------------------------
template<typename F, typename... Args>
static inline void launch_pdl(F kern, dim3 grid, size_t shmem, Args... args) {
    cudaLaunchConfig_t cfg = {};
    cfg.gridDim = grid;
    cfg.blockDim = dim3(320, 1, 1);
    cfg.dynamicSmemBytes = shmem;
    cfg.stream = 0;
    cudaLaunchAttribute attr[1];
    attr[0].id = cudaLaunchAttributeProgrammaticStreamSerialization;
    attr[0].val.programmaticStreamSerializationAllowed = 1;
    cfg.attrs = attr;
    cfg.numAttrs = 1;
    cudaLaunchKernelEx(&cfg, kern, args...);
}

// ===========================================================================
extern "C" void kernel_launch(void* const* d_in, const int* in_sizes, int n_in,
                              void* d_out, int out_size) {
    const float* feature = (const float*)d_in[0];   // [1024, 2048]
    const float* inp     = (const float*)d_in[1];   // [1, 80, 300]
    const float* A       = (const float*)d_in[2];   // [80, 80]
    const float* Wgc1    = (const float*)d_in[3];   // [300, 1024]
    const float* Wgc2    = (const float*)d_in[4];   // [1024, 2048]
    const float* Wimg    = (const float*)d_in[5];   // [8000, 2048]
    const float* bimg    = (const float*)d_in[6];   // [8000]
    const float* Wcls    = (const float*)d_in[7];   // [8000, 2048]
    const float* bcls    = (const float*)d_in[8];   // [8000]
    float* out = (float*)d_out;                     // [1024, 80] row-major

    float* buf;
    cudaGetSymbolAddress((void**)&buf, g_buf);
    float* adj = buf + OFF_ADJ;
    float* t   = buf + OFF_T;
    float* P   = buf + OFF_P;
    float* Q   = buf + OFF_Q;
    float* x1  = buf + OFF_X1;
    float* x2  = buf + OFF_X2;
    float* cls = buf + OFF_CLS;
    float* Mm  = buf + OFF_M;

    const float* fnul = nullptr;
    float* nul = nullptr;

    cudaFuncSetAttribute(hgemm<false>,
                         cudaFuncAttributeMaxDynamicSharedMemorySize, HS_BYTES);
    cudaFuncSetAttribute(hgemm<true>,
                         cudaFuncAttributeMaxDynamicSharedMemorySize, HS_BYTES);

    // Zero all hgemm targets (P..M contiguous) + out + t, plus adj, one launch.
    {
        int ntot = SZ_ZERO + BB * CC;
        int nblk = (ntot + 255) / 256 + 1;   // +1: adj block
        zero_adj_kernel<<<nblk, 256>>>(P, SZ_ZERO, out, BB * CC, A, adj, t);
    }

    // P = adj @ inp0                 [80,300]  K=80, split 4 (chunk 20)
    launch_pdl(hgemm<false>, dim3(3, 4), (size_t)HS_BYTES,
        (const float*)adj, inp, P, fnul, fnul, fnul, nul,
        DW, CC, CC, CC, DW, DWP, 0, 0);

    // x1 = P @ W_gc1                 [80,1024] K=304 pad (Kb=300), split 4
    launch_pdl(hgemm<false>, dim3(8, 4), (size_t)HS_BYTES,
        (const float*)P, Wgc1, x1, fnul, fnul, fnul, nul,
        1024, DWP, DW, DWP, 1024, 1024, 0, 0);

    // Q = adj @ leaky(x1)            [80,1024] K=80, split 4 (chunk 20)
    launch_pdl(hgemm<false>, dim3(8, 4), (size_t)HS_BYTES,
        (const float*)adj, (const float*)x1, Q, fnul, fnul, fnul, nul,
        1024, CC, CC, CC, 1024, 1024, 1, 0);

    // x2 = Q @ W_gc2                 [80,2048] K=1024, split 16 (256 blk)
    launch_pdl(hgemm<false>, dim3(16, 16), (size_t)HS_BYTES,
        (const float*)Q, Wgc2, x2, fnul, fnul, fnul, nul,
        2048, 1024, 1024, 1024, 2048, 2048, 0, 0);

    // cls = x2 @ W_cls^T + b_cls     [80,8000] K=2048, split 4 (252 blk)
    // fused: t[c] += sum_n cls_partial[c,n] * b_img[n]
    launch_pdl(hgemm<true>, dim3(63, 4), (size_t)HS_BYTES,
        (const float*)x2, Wcls, cls, bcls, fnul, bimg, t,
        JJ, 2048, 2048, 2048, 2048, JJ, 0, 0);

    // M = cls @ W_img                [80,2048] K=8000, split 16 (256 blk)
    launch_pdl(hgemm<false>, dim3(16, 16), (size_t)HS_BYTES,
        (const float*)cls, Wimg, Mm, fnul, fnul, fnul, nul,
        2048, JJ, JJ, JJ, 2048, 2048, 0, 0);

    // out^T: C[c,b] = Mm[c,:].feature[b,:] + t[c] -> out[b*80+c]
    //                                [80,1024] K=2048, split 32 (256 blk)
    launch_pdl(hgemm<true>, dim3(8, 32), (size_t)HS_BYTES,
        (const float*)Mm, feature, out, fnul, (const float*)t, fnul, nul,
        BB, 2048, 2048, 2048, 2048, CC, 0, 1);
}

// round 17
// speedup vs baseline: 1.2754x; 1.0899x over previous
#include <cuda_runtime.h>
#include <cuda_bf16.h>
#include <cstdint>

// Problem dims
#define BB 1024
#define CC 80
#define DW 300
#define DWP 304          // padded DW for aligned float4 rows
#define JJ 8000
#define ICH 2048

// ---- scratch layout in one device global (no allocations allowed) ----------
// Non-zeroed: adj. Zeroed: t (in adj block) + contiguous P..M (hgemm targets)
#define OFF_ADJ 0
#define SZ_ADJ  (CC*CC)
#define OFF_T   (OFF_ADJ + SZ_ADJ)
#define SZ_T    (CC)
#define OFF_P   (OFF_T + SZ_T)
#define SZ_P    (CC*DWP)
#define OFF_Q   (OFF_P + SZ_P)
#define SZ_Q    (CC*1024)
#define OFF_X1  (OFF_Q + SZ_Q)
#define SZ_X1   (CC*1024)
#define OFF_X2  (OFF_X1 + SZ_X1)
#define SZ_X2   (CC*2048)
#define OFF_CLS (OFF_X2 + SZ_X2)
#define SZ_CLS  (CC*JJ)
#define OFF_M   (OFF_CLS + SZ_CLS)
#define SZ_M    (CC*2048)
#define SZ_ZERO (SZ_P + SZ_Q + SZ_X1 + SZ_X2 + SZ_CLS + SZ_M)
#define SZ_TOT  (OFF_M + SZ_M)

__device__ float g_buf[SZ_TOT];

// ===========================================================================
// helpers
// ===========================================================================
__device__ __forceinline__ uint32_t smem_u32(const void* p) {
    uint32_t a;
    asm("{ .reg .u64 t; cvta.to.shared.u64 t, %1; cvt.u32.u64 %0, t; }"
        : "=r"(a) : "l"(p));
    return a;
}
__device__ __forceinline__ void ldsm4(uint32_t& r0, uint32_t& r1,
                                      uint32_t& r2, uint32_t& r3, uint32_t addr) {
    asm volatile("ldmatrix.sync.aligned.m8n8.x4.shared.b16 {%0,%1,%2,%3}, [%4];"
                 : "=r"(r0), "=r"(r1), "=r"(r2), "=r"(r3) : "r"(addr));
}
__device__ __forceinline__ void mma16816(float* c,
        uint32_t a0, uint32_t a1, uint32_t a2, uint32_t a3,
        uint32_t b0, uint32_t b1) {
    asm volatile("mma.sync.aligned.m16n8k16.row.col.f32.bf16.bf16.f32 "
                 "{%0,%1,%2,%3}, {%4,%5,%6,%7}, {%8,%9}, {%0,%1,%2,%3};"
                 : "+f"(c[0]), "+f"(c[1]), "+f"(c[2]), "+f"(c[3])
                 : "r"(a0), "r"(a1), "r"(a2), "r"(a3), "r"(b0), "r"(b1));
}
// fp32x4 -> packed bf16 hi pair-quad + lo pair-quad, via bf16x2 cvt.
__device__ __forceinline__ void split4(float4 v, uint2& hi, uint2& lo) {
    uint32_t h01, h23;
    asm("cvt.rn.bf16x2.f32 %0, %1, %2;" : "=r"(h01) : "f"(v.y), "f"(v.x));
    asm("cvt.rn.bf16x2.f32 %0, %1, %2;" : "=r"(h23) : "f"(v.w), "f"(v.z));
    float h0 = __uint_as_float(h01 << 16);
    float h1 = __uint_as_float(h01 & 0xFFFF0000u);
    float h2 = __uint_as_float(h23 << 16);
    float h3 = __uint_as_float(h23 & 0xFFFF0000u);
    uint32_t l01, l23;
    asm("cvt.rn.bf16x2.f32 %0, %1, %2;" : "=r"(l01) : "f"(v.y - h1), "f"(v.x - h0));
    asm("cvt.rn.bf16x2.f32 %0, %1, %2;" : "=r"(l23) : "f"(v.w - h3), "f"(v.z - h2));
    hi.x = h01; hi.y = h23; lo.x = l01; lo.y = l23;
}
__device__ __forceinline__ float4 leaky4(float4 v) {
    v.x = v.x > 0.f ? v.x : 0.2f * v.x;
    v.y = v.y > 0.f ? v.y : 0.2f * v.y;
    v.z = v.z > 0.f ? v.z : 0.2f * v.z;
    v.w = v.w > 0.f ? v.w : 0.2f * v.w;
    return v;
}

// ===========================================================================
// Tensor-core GEMM via mma.sync (HMMA; baseline PTX, safe at compute_103):
//   C[80, N] += A[80, K] * op(B), split bf16 (hi/lo, 3 terms), fp32 accum.
// Tile 80 x 128, k-tile 32 fp32 (smem 65KB double-buffered -> 2 CTA/SM).
// 320 threads = 10 warps (5m x 2n); warp m16 x n64 -> 8 acc chains.
// MAINLOOP (fragment-reuse form): per k16, aH/aL loaded once, B_hi frags
// used by both aH and aL terms before being overwritten by B_lo:
//   ldsm aH,aL ; ldsm b<-B_hi ; mma aH*b, aL*b ; ldsm b<-B_lo ; mma aH*b
// -> 10 ldsm + 24 mma per k16 (was 15 + 24): smem-crossbar pressure -33%.
// Split-K over gridDim.y (chunk % 4 == 0); atomicAdd into pre-zeroed C.
// Optional fused dot reduction: dot_out[m] += sum_n C_v[m,n]*dot_vec[n].
// PDL: griddepcontrol.wait before any dependent read; launch_dependents at end.
// ===========================================================================
#define HRS 40
#define HA_ELEM (80 * HRS)                        // 3200
#define HB_ELEM (128 * HRS)                       // 5120
#define HBUF_ELEM (2 * HA_ELEM + 2 * HB_ELEM)     // 16640 bf16
#define HS_BYTES (2 * HBUF_ELEM * 2)              // 66560 B

template<bool BNK>
__global__ void __launch_bounds__(320, 2)
hgemm(const float* __restrict__ A, const float* __restrict__ B,
      float* __restrict__ C, const float* __restrict__ bias_n,
      const float* __restrict__ bias_m,
      const float* __restrict__ dot_vec, float* __restrict__ dot_out,
      int N, int K, int Kb, int lda, int ldb, int ldc, int leaky_b, int transC) {
    extern __shared__ __nv_bfloat16 hs[];
    const uint32_t sbase = smem_u32(hs);

    const int tid  = threadIdx.x;
    const int lane = tid & 31;
    const int wid  = tid >> 5;          // 0..9
    const int wm   = wid >> 1;          // 0..4 -> rows wm*16
    const int wn   = wid & 1;           // 0..1 -> cols wn*64
    const int n0   = blockIdx.x * 128;

    const int chunk = (K + gridDim.y - 1) / (int)gridDim.y;
    const int kb = min(K, (int)blockIdx.y * chunk);
    const int ke = min(K, kb + chunk);
    const int ntiles = (ke - kb + 31) >> 5;
    const int keB = min(ke, Kb);

    const uint32_t oAL = HA_ELEM;
    const uint32_t oBH = 2 * HA_ELEM, oBL = 2 * HA_ELEM + HB_ELEM;

    // ---- staging registers (k-tile 32)
    uint2 aH[2], aL[2];
    uint2 bH[4], bL[4];

    auto loadA = [&](int k0) {
        #pragma unroll
        for (int i = 0; i < 2; i++) {
            int idx = tid + i * 320;            // 80 rows x 8 float4 = 640
            int row = idx >> 3, c4 = idx & 7;
            int gk = k0 + c4 * 4;
            float4 v = make_float4(0.f, 0.f, 0.f, 0.f);
            if (gk < ke) v = *(const float4*)(A + (size_t)row * lda + gk);
            split4(v, aH[i], aL[i]);
        }
    };
    auto storeA = [&](int buf) {
        __nv_bfloat16* base = hs + buf * HBUF_ELEM;
        #pragma unroll
        for (int i = 0; i < 2; i++) {
            int idx = tid + i * 320;
            int row = idx >> 3, c4 = idx & 7;
            uint32_t off = row * HRS + c4 * 4;
            *(uint2*)(base + off) = aH[i];
            *(uint2*)(base + oAL + off) = aL[i];
        }
    };
    auto loadB = [&](int k0) {
        if (BNK) {
            #pragma unroll
            for (int i = 0; i < 4; i++) {
                int idx = tid + i * 320;        // 128 rows x 8 float4 = 1024
                if (idx >= 1024) continue;
                int row = idx >> 3, c4 = idx & 7;
                int gn = n0 + row, gk = k0 + c4 * 4;
                float4 v = make_float4(0.f, 0.f, 0.f, 0.f);
                if (gk < keB && gn < N)
                    v = *(const float4*)(B + (size_t)gn * ldb + gk);
                split4(v, bH[i], bL[i]);
            }
        } else {
            // B[K,N]: groups of 4 k-rows x 4 n-cols; 8 kq x 32 nq = 256 groups
            if (tid < 256) {
                int nq = tid & 31, kq = tid >> 5;
                int gn = n0 + nq * 4, gkb = k0 + kq * 4;
                float4 r[4];
                #pragma unroll
                for (int rr = 0; rr < 4; rr++) {
                    int gk = gkb + rr;
                    float4 v = make_float4(0.f, 0.f, 0.f, 0.f);
                    if (gk < keB && gn < N)
                        v = *(const float4*)(B + (size_t)gk * ldb + gn);
                    if (leaky_b) v = leaky4(v);
                    r[rr] = v;
                }
                #pragma unroll
                for (int j = 0; j < 4; j++) {
                    float4 kv = make_float4(((float*)&r[0])[j], ((float*)&r[1])[j],
                                            ((float*)&r[2])[j], ((float*)&r[3])[j]);
                    split4(kv, bH[j], bL[j]);
                }
            }
        }
    };
    auto storeB = [&](int buf) {
        __nv_bfloat16* base = hs + buf * HBUF_ELEM;
        if (BNK) {
            #pragma unroll
            for (int i = 0; i < 4; i++) {
                int idx = tid + i * 320;
                if (idx >= 1024) continue;
                int row = idx >> 3, c4 = idx & 7;
                uint32_t off = row * HRS + c4 * 4;
                *(uint2*)(base + oBH + off) = bH[i];
                *(uint2*)(base + oBL + off) = bL[i];
            }
        } else {
            if (tid < 256) {
                int nq = tid & 31, kq = tid >> 5;
                #pragma unroll
                for (int j = 0; j < 4; j++) {
                    uint32_t off = (nq * 4 + j) * HRS + kq * 4;
                    *(uint2*)(base + oBH + off) = bH[j];
                    *(uint2*)(base + oBL + off) = bL[j];
                }
            }
        }
    };

    float acc[8][4];
    #pragma unroll
    for (int i = 0; i < 8; i++)
        #pragma unroll
        for (int j = 0; j < 4; j++) acc[i][j] = 0.f;

    // PDL: block until the upstream grid (our input producer) is complete.
    asm volatile("griddepcontrol.wait;" ::: "memory");

    loadA(kb); loadB(kb);
    storeA(0); storeB(0);
    __syncthreads();

    const int grp = lane >> 3, lr = lane & 7;
    const uint32_t aRow = wm * 16 + ((grp & 1) << 3) + lr;
    const uint32_t aColOff = (grp >> 1) << 3;
    const uint32_t bRowBase = wn * 64 + ((grp >> 1) << 3) + lr;
    const uint32_t bColOff = (grp & 1) << 3;

    for (int t = 0; t < ntiles; t++) {
        const int cur = t & 1;
        const bool more = (t + 1 < ntiles);
        if (more) { int k0n = kb + (t + 1) * 32; loadA(k0n); loadB(k0n); }

        const uint32_t bufb = sbase + cur * (HBUF_ELEM * 2);

        #pragma unroll
        for (int k16 = 0; k16 < 2; k16++) {
            const uint32_t aOff = (aRow * HRS + k16 * 16 + aColOff) * 2;
            // A fragments: hi and lo, each loaded ONCE per k16
            uint32_t ah0, ah1, ah2, ah3, al0, al1, al2, al3;
            ldsm4(ah0, ah1, ah2, ah3, bufb + aOff);
            ldsm4(al0, al1, al2, al3, bufb + oAL * 2 + aOff);

            // B_hi fragments -> used by BOTH aH and aL terms
            uint32_t b[16];
            #pragma unroll
            for (int h = 0; h < 4; h++) {
                ldsm4(b[h*4], b[h*4+1], b[h*4+2], b[h*4+3],
                      bufb + oBH * 2 +
                      ((bRowBase + h * 16) * HRS + k16 * 16 + bColOff) * 2);
            }
            #pragma unroll
            for (int nt = 0; nt < 8; nt++)
                mma16816(acc[nt], ah0, ah1, ah2, ah3, b[nt*2], b[nt*2+1]);
            #pragma unroll
            for (int nt = 0; nt < 8; nt++)
                mma16816(acc[nt], al0, al1, al2, al3, b[nt*2], b[nt*2+1]);

            // B_lo fragments overwrite b[] -> aH term only
            #pragma unroll
            for (int h = 0; h < 4; h++) {
                ldsm4(b[h*4], b[h*4+1], b[h*4+2], b[h*4+3],
                      bufb + oBL * 2 +
                      ((bRowBase + h * 16) * HRS + k16 * 16 + bColOff) * 2);
            }
            #pragma unroll
            for (int nt = 0; nt < 8; nt++)
                mma16816(acc[nt], ah0, ah1, ah2, ah3, b[nt*2], b[nt*2+1]);
        }

        if (more) { storeA(cur ^ 1); storeB(cur ^ 1); }
        __syncthreads();
    }

    // ---- epilogue (+ optional fused dot reduction into dot_out)
    const bool first = (blockIdx.y == 0);
    const int r0 = wm * 16 + (lane >> 2);
    const int cb = n0 + wn * 64 + (lane & 3) * 2;
    float s0 = 0.f, s1 = 0.f;
    #pragma unroll
    for (int nt = 0; nt < 8; nt++) {
        #pragma unroll
        for (int e = 0; e < 4; e++) {
            int gm = r0 + ((e >> 1) << 3);
            int gn = cb + nt * 8 + (e & 1);
            if (gn >= N) continue;
            float v = acc[nt][e];
            if (first) {
                if (bias_n) v += bias_n[gn];
                if (bias_m) v += bias_m[gm];
            }
            if (dot_out) {
                float bv = dot_vec[gn] * v;
                if (e >> 1) s1 += bv; else s0 += bv;
            }
            float* dst = transC ? (C + (size_t)gn * ldc + gm)
                                : (C + (size_t)gm * ldc + gn);
            atomicAdd(dst, v);
        }
    }
    if (dot_out) {
        s0 += __shfl_xor_sync(0xFFFFFFFFu, s0, 1);
        s0 += __shfl_xor_sync(0xFFFFFFFFu, s0, 2);
        s1 += __shfl_xor_sync(0xFFFFFFFFu, s1, 1);
        s1 += __shfl_xor_sync(0xFFFFFFFFu, s1, 2);
        if ((lane & 3) == 0) {
            atomicAdd(dot_out + r0, s0);
            atomicAdd(dot_out + r0 + 8, s1);
        }
    }
    // PDL: all our writes are done; allow the dependent grid to proceed.
    asm volatile("griddepcontrol.launch_dependents;" ::: "memory");
}

// ===========================================================================
// zero + adj in one launch: last block computes adj (and zeroes t), the rest
// zero the hgemm scratch + out.
// ===========================================================================
__global__ void zero_adj_kernel(float* __restrict__ z, int nz,
                                float* __restrict__ o, int no,
                                const float* __restrict__ A,
                                float* __restrict__ adj,
                                float* __restrict__ t) {
    if (blockIdx.x == gridDim.x - 1) {
        __shared__ float D[CC];
        int tid = threadIdx.x;
        if (tid < CC) {
            float s = 0.f;
            #pragma unroll 4
            for (int j = 0; j < CC; j++) s += A[tid * CC + j];
            D[tid] = 1.0f / sqrtf(s);
            t[tid] = 0.f;
        }
        __syncthreads();
        for (int idx = tid; idx < CC * CC; idx += blockDim.x) {
            int i = idx / CC, j = idx % CC;
            adj[idx] = D[i] * A[j * CC + i] * D[j];
        }
        return;
    }
    int i = blockIdx.x * blockDim.x + threadIdx.x;
    if (i < nz) z[i] = 0.f;
    else if (i - nz < no) o[i - nz] = 0.f;
}

// ---- PDL launch helper ----------------------------------------------------
template<typename F, typename... Args>
static inline void launch_pdl(F kern, dim3 grid, size_t shmem, Args... args) {
    cudaLaunchConfig_t cfg = {};
    cfg.gridDim = grid;
    cfg.blockDim = dim3(320, 1, 1);
    cfg.dynamicSmemBytes = shmem;
    cfg.stream = 0;
    cudaLaunchAttribute attr[1];
    attr[0].id = cudaLaunchAttributeProgrammaticStreamSerialization;
    attr[0].val.programmaticStreamSerializationAllowed = 1;
    cfg.attrs = attr;
    cfg.numAttrs = 1;
    cudaLaunchKernelEx(&cfg, kern, args...);
}

// ===========================================================================
extern "C" void kernel_launch(void* const* d_in, const int* in_sizes, int n_in,
                              void* d_out, int out_size) {
    const float* feature = (const float*)d_in[0];   // [1024, 2048]
    const float* inp     = (const float*)d_in[1];   // [1, 80, 300]
    const float* A       = (const float*)d_in[2];   // [80, 80]
    const float* Wgc1    = (const float*)d_in[3];   // [300, 1024]
    const float* Wgc2    = (const float*)d_in[4];   // [1024, 2048]
    const float* Wimg    = (const float*)d_in[5];   // [8000, 2048]
    const float* bimg    = (const float*)d_in[6];   // [8000]
    const float* Wcls    = (const float*)d_in[7];   // [8000, 2048]
    const float* bcls    = (const float*)d_in[8];   // [8000]
    float* out = (float*)d_out;                     // [1024, 80] row-major

    float* buf;
    cudaGetSymbolAddress((void**)&buf, g_buf);
    float* adj = buf + OFF_ADJ;
    float* t   = buf + OFF_T;
    float* P   = buf + OFF_P;
    float* Q   = buf + OFF_Q;
    float* x1  = buf + OFF_X1;
    float* x2  = buf + OFF_X2;
    float* cls = buf + OFF_CLS;
    float* Mm  = buf + OFF_M;

    const float* fnul = nullptr;
    float* nul = nullptr;

    cudaFuncSetAttribute(hgemm<false>,
                         cudaFuncAttributeMaxDynamicSharedMemorySize, HS_BYTES);
    cudaFuncSetAttribute(hgemm<true>,
                         cudaFuncAttributeMaxDynamicSharedMemorySize, HS_BYTES);

    // Zero all hgemm targets (P..M contiguous) + out + t, plus adj, one launch.
    {
        int ntot = SZ_ZERO + BB * CC;
        int nblk = (ntot + 255) / 256 + 1;   // +1: adj block
        zero_adj_kernel<<<nblk, 256>>>(P, SZ_ZERO, out, BB * CC, A, adj, t);
    }

    // P = adj @ inp0                 [80,300]  K=80, split 4 (chunk 20)
    launch_pdl(hgemm<false>, dim3(3, 4), (size_t)HS_BYTES,
        (const float*)adj, inp, P, fnul, fnul, fnul, nul,
        DW, CC, CC, CC, DW, DWP, 0, 0);

    // x1 = P @ W_gc1                 [80,1024] K=304 pad (Kb=300), split 4
    launch_pdl(hgemm<false>, dim3(8, 4), (size_t)HS_BYTES,
        (const float*)P, Wgc1, x1, fnul, fnul, fnul, nul,
        1024, DWP, DW, DWP, 1024, 1024, 0, 0);

    // Q = adj @ leaky(x1)            [80,1024] K=80, split 4 (chunk 20)
    launch_pdl(hgemm<false>, dim3(8, 4), (size_t)HS_BYTES,
        (const float*)adj, (const float*)x1, Q, fnul, fnul, fnul, nul,
        1024, CC, CC, CC, 1024, 1024, 1, 0);

    // x2 = Q @ W_gc2                 [80,2048] K=1024, split 16 (256 blk)
    launch_pdl(hgemm<false>, dim3(16, 16), (size_t)HS_BYTES,
        (const float*)Q, Wgc2, x2, fnul, fnul, fnul, nul,
        2048, 1024, 1024, 1024, 2048, 2048, 0, 0);

    // cls = x2 @ W_cls^T + b_cls     [80,8000] K=2048, split 4 (252 blk)
    // fused: t[c] += sum_n cls_partial[c,n] * b_img[n]
    launch_pdl(hgemm<true>, dim3(63, 4), (size_t)HS_BYTES,
        (const float*)x2, Wcls, cls, bcls, fnul, bimg, t,
        JJ, 2048, 2048, 2048, 2048, JJ, 0, 0);

    // M = cls @ W_img                [80,2048] K=8000, split 16 (256 blk)
    launch_pdl(hgemm<false>, dim3(16, 16), (size_t)HS_BYTES,
        (const float*)cls, Wimg, Mm, fnul, fnul, fnul, nul,
        2048, JJ, JJ, JJ, 2048, 2048, 0, 0);

    // out^T: C[c,b] = Mm[c,:].feature[b,:] + t[c] -> out[b*80+c]
    //                                [80,1024] K=2048, split 32 (256 blk)
    launch_pdl(hgemm<true>, dim3(8, 32), (size_t)HS_BYTES,
        (const float*)Mm, feature, out, fnul, (const float*)t, fnul, nul,
        BB, 2048, 2048, 2048, 2048, CC, 0, 1);
}